// round 16
// baseline (speedup 1.0000x reference)
#include <cuda_runtime.h>
#include <cuda_bf16.h>

#define MMAX 50000
#define HNB 32
#define CIN 128
#define CMID 32
#define KPTS 15
#define CPG 16
#define BNEPS 1e-5f
#define NEG 0.1f
#define FULLM 0xffffffffu

// scratch (device globals; no allocation allowed)
__device__ float g_x1[MMAX * CMID];   // unary1 output (raw, then BN1+lrelu in place)
__device__ float g_cv[MMAX * CMID];   // conv output (raw pre-BN)
__device__ float4 g_pts4[MMAX];       // padded support points (x,y,z,0)
// stats raw sums: [0:32) sum1 [32:64) sq1 [64:96) sum2 [96:128) sq2 [128:256) sum3 [256:384) sq3
__device__ float g_stats[384];

// ---------- prep: zero stats + pad s_pts to float4 ----------
__global__ __launch_bounds__(256) void k_prep(const float* __restrict__ s_pts, int M) {
    if (blockIdx.x == 0) {
        for (int i = threadIdx.x; i < 384; i += 256) g_stats[i] = 0.f;
    }
    int stride = gridDim.x * blockDim.x;
    for (int i = blockIdx.x * blockDim.x + threadIdx.x; i < M; i += stride) {
        g_pts4[i] = make_float4(s_pts[3*i], s_pts[3*i + 1], s_pts[3*i + 2], 0.f);
    }
}

// ---------- unary1: y1 = s_feats(M,128) @ w_u1(128,32), 4 rows/warp ----------
__global__ __launch_bounds__(256, 4) void k_unary1(const float* __restrict__ sfeat,
                                                   const float* __restrict__ w_u1, int M) {
    __shared__ float4 swt[32 * 32];     // [chunk q][c] = w[4q..4q+3][c], 16 KB
    __shared__ float4 xs[8][4][32];     // [warp][row][chunk], 16 KB
    __shared__ float red[8][2][CMID];
    int t = threadIdx.x;
    for (int i = t; i < CIN * CMID; i += 256) {
        int c = i & 31, ii = i >> 5;
        ((float*)&swt[(ii >> 2) * 32 + c])[ii & 3] = w_u1[i];
    }
    __syncthreads();
    int warp = t >> 5, lane = t & 31;
    int G = (M + 3) >> 2;
    int wgid = blockIdx.x * 8 + warp;
    int nw = gridDim.x * 8;
    float lsum = 0.f, lsq = 0.f;
    for (int g = wgid; g < G; g += nw) {
        int m0 = g << 2;
        #pragma unroll
        for (int r = 0; r < 4; r++) {
            int m = m0 + r;
            float4 v = make_float4(0.f, 0.f, 0.f, 0.f);
            if (m < M) v = ((const float4*)(sfeat + (size_t)m * CIN))[lane];
            xs[warp][r][lane] = v;
        }
        __syncwarp();
        float acc[4] = {0.f, 0.f, 0.f, 0.f};
        #pragma unroll 4
        for (int q = 0; q < 32; q++) {
            float4 w4 = swt[q * 32 + lane];      // conflict-free LDS.128
            #pragma unroll
            for (int r = 0; r < 4; r++) {
                float4 x4 = xs[warp][r][q];      // broadcast LDS.128
                acc[r] = fmaf(x4.x, w4.x, acc[r]);
                acc[r] = fmaf(x4.y, w4.y, acc[r]);
                acc[r] = fmaf(x4.z, w4.z, acc[r]);
                acc[r] = fmaf(x4.w, w4.w, acc[r]);
            }
        }
        #pragma unroll
        for (int r = 0; r < 4; r++) {
            int m = m0 + r;
            if (m < M) {
                g_x1[(size_t)m * CMID + lane] = acc[r];
                lsum += acc[r];
                lsq = fmaf(acc[r], acc[r], lsq);
            }
        }
        __syncwarp();
    }
    red[warp][0][lane] = lsum; red[warp][1][lane] = lsq;
    __syncthreads();
    if (warp == 0) {
        float s = 0.f, q = 0.f;
        #pragma unroll
        for (int w = 0; w < 8; w++) { s += red[w][0][lane]; q += red[w][1][lane]; }
        atomicAdd(&g_stats[lane], s);
        atomicAdd(&g_stats[32 + lane], q);
    }
}

// ---------- bn1: apply BN1 + lrelu to g_x1 in place (float4, persistent) ----------
__global__ __launch_bounds__(256) void k_bn1(const float* __restrict__ g1,
                                             const float* __restrict__ b1,
                                             float invM, int M) {
    __shared__ float bn1[64];
    int t = threadIdx.x;
    if (t < 32) {
        float s = g_stats[t], q = g_stats[32 + t];
        float mm = s * invM;
        float v = q * invM - mm * mm;
        float is = rsqrtf(v + BNEPS);
        float sc = is * g1[t];
        bn1[t] = sc;
        bn1[32 + t] = b1[t] - mm * sc;
    }
    __syncthreads();
    int n = M * 8;                     // float4 count
    int stride = gridDim.x * 256;
    for (int i = blockIdx.x * 256 + t; i < n; i += stride) {
        int ch = i & 7;
        float4 sc4 = ((const float4*)bn1)[ch];
        float4 sh4 = ((const float4*)(bn1 + 32))[ch];
        float4 v = ((const float4*)g_x1)[i];
        float y;
        y = fmaf(v.x, sc4.x, sh4.x); v.x = fmaxf(y, NEG * y);
        y = fmaf(v.y, sc4.y, sh4.y); v.y = fmaxf(y, NEG * y);
        y = fmaf(v.z, sc4.z, sh4.z); v.z = fmaxf(y, NEG * y);
        y = fmaf(v.w, sc4.w, sh4.w); v.w = fmaxf(y, NEG * y);
        ((float4*)g_x1)[i] = v;
    }
}

// ---------- KPInv conv: one warp per point, float4 gather/contract ----------
__global__ __launch_bounds__(256) void k_conv(const float* __restrict__ q_pts,
                                              const int* __restrict__ nidx,
                                              const float* __restrict__ kp,
                                              const float* __restrict__ w_g1,
                                              const float* __restrict__ b_g1,
                                              const float* __restrict__ w_g2,
                                              const float* __restrict__ b_g2,
                                              int M) {
    __shared__ float4 nf4_s[8][32][8];  // 32 KB: [warp][h][cq]
    __shared__ float4 wg1q[64];         // [u][cq]: w_g1 transposed, float4 over c
    __shared__ float kps[KPTS * 3];
    __shared__ float kpn[KPTS];
    __shared__ float bg1s[8];
    __shared__ float wg2s[8 * 30];
    __shared__ float bg2s[30];
    __shared__ float wbuf[8][32];
    __shared__ float2 abuf[8][32];
    __shared__ float4 redS[8][8], redQ[8][8];
    int t = threadIdx.x;
    if (t < KPTS * 3) kps[t] = kp[t];
    if (t >= 64 && t < 64 + KPTS) {
        int k = t - 64;
        kpn[k] = kp[k*3]*kp[k*3] + kp[k*3+1]*kp[k*3+1] + kp[k*3+2]*kp[k*3+2];
    }
    for (int i = t; i < 256; i += blockDim.x) {
        int u = i >> 5, c = i & 31;
        ((float*)wg1q)[u * 32 + c] = w_g1[c * 8 + u];
    }
    if (t >= 96 && t < 104) bg1s[t - 96] = b_g1[t - 96];
    for (int i = t; i < 240; i += blockDim.x) wg2s[i] = w_g2[i];
    if (t >= 128 && t < 158) bg2s[t - 128] = b_g2[t - 128];
    __syncthreads();

    int warp = t >> 5, lane = t & 31;
    int hs = lane >> 3, cq = lane & 7, hi = cq >> 2;
    int wgid = blockIdx.x * 8 + warp;
    int nw = gridDim.x * 8;
    float4 ps = make_float4(0.f, 0.f, 0.f, 0.f);
    float4 pq = make_float4(0.f, 0.f, 0.f, 0.f);

    for (int m = wgid; m < M; m += nw) {
        // lane = neighbor h: index + geometry (position via one LDG.128)
        int j = nidx[(size_t)m * HNB + lane];
        int off = j << 5;
        float qx = q_pts[m*3], qy = q_pts[m*3+1], qz = q_pts[m*3+2];
        float4 sp = g_pts4[j];
        float nx = sp.x - qx;
        float ny = sp.y - qy;
        float nz = sp.z - qz;
        float n2 = nx*nx + ny*ny + nz*nz;
        // gather float4 (already BN'd+lrelu'd): lane = (h = 4i+hs, channels cq*4..+3)
        float4 cm = make_float4(-3.4e38f, -3.4e38f, -3.4e38f, -3.4e38f);
        #pragma unroll
        for (int i = 0; i < 8; i++) {
            int h = i * 4 + hs;
            int oh = __shfl_sync(FULLM, off, h);
            float4 v = *(const float4*)(g_x1 + oh + cq * 4);
            nf4_s[warp][h][cq] = v;
            cm.x = fmaxf(cm.x, v.x); cm.y = fmaxf(cm.y, v.y);
            cm.z = fmaxf(cm.z, v.z); cm.w = fmaxf(cm.w, v.w);
        }
        // reduce max over hs groups (xor 8, 16)
        cm.x = fmaxf(cm.x, __shfl_xor_sync(FULLM, cm.x, 8));
        cm.y = fmaxf(cm.y, __shfl_xor_sync(FULLM, cm.y, 8));
        cm.z = fmaxf(cm.z, __shfl_xor_sync(FULLM, cm.z, 8));
        cm.w = fmaxf(cm.w, __shfl_xor_sync(FULLM, cm.w, 8));
        cm.x = fmaxf(cm.x, __shfl_xor_sync(FULLM, cm.x, 16));
        cm.y = fmaxf(cm.y, __shfl_xor_sync(FULLM, cm.y, 16));
        cm.z = fmaxf(cm.z, __shfl_xor_sync(FULLM, cm.z, 16));
        cm.w = fmaxf(cm.w, __shfl_xor_sync(FULLM, cm.w, 16));
        // MLP: per-lane partial dot over 4 channels, sum over cq via xor 1,2,4
        float hp[8];
        #pragma unroll
        for (int u = 0; u < 8; u++) {
            float4 w4 = wg1q[u * 8 + cq];
            float p = cm.x * w4.x;
            p = fmaf(cm.y, w4.y, p);
            p = fmaf(cm.z, w4.z, p);
            p = fmaf(cm.w, w4.w, p);
            hp[u] = p;
        }
        #pragma unroll
        for (int o = 1; o <= 4; o <<= 1)
            #pragma unroll
            for (int u = 0; u < 8; u++) hp[u] += __shfl_xor_sync(FULLM, hp[u], o);
        // w[t] = b_g2[t] + lrelu(hp+b) @ w_g2, layout (K,G): w[k][g] at 2k+g
        float wt = 0.f;
        if (lane < 30) {
            wt = bg2s[lane];
            #pragma unroll
            for (int u = 0; u < 8; u++) {
                float v = hp[u] + bg1s[u];
                v = fmaxf(v, NEG * v);
                wt = fmaf(v, wg2s[u * 30 + lane], wt);
            }
        }
        wbuf[warp][lane] = wt;
        __syncwarp();
        // collapse K with transient influence (lane = h)
        float a0 = 0.f, a1 = 0.f;
        #pragma unroll
        for (int k = 0; k < KPTS; k++) {
            float dot = nx*kps[k*3] + ny*kps[k*3+1] + nz*kps[k*3+2];
            float d2 = n2 + kpn[k] - 2.f * dot;
            float d = sqrtf(fmaxf(d2, 0.f));
            float infl = fmaxf(1.f - d, 0.f);
            a0 = fmaf(wbuf[warp][2*k],     infl, a0);
            a1 = fmaf(wbuf[warp][2*k + 1], infl, a1);
        }
        abuf[warp][lane] = make_float2(a0, a1);
        __syncwarp();
        // out[c] = sum_h a[h][g(c)] * nf[h][c], vectorized: lane = (hs, cq)
        float4 o4 = make_float4(0.f, 0.f, 0.f, 0.f);
        #pragma unroll
        for (int i = 0; i < 8; i++) {
            int h = i * 4 + hs;
            float a = ((const float*)abuf[warp])[h * 2 + hi];  // group select in addr
            float4 v = nf4_s[warp][h][cq];
            o4.x = fmaf(a, v.x, o4.x);
            o4.y = fmaf(a, v.y, o4.y);
            o4.z = fmaf(a, v.z, o4.z);
            o4.w = fmaf(a, v.w, o4.w);
        }
        o4.x += __shfl_xor_sync(FULLM, o4.x, 8);
        o4.y += __shfl_xor_sync(FULLM, o4.y, 8);
        o4.z += __shfl_xor_sync(FULLM, o4.z, 8);
        o4.w += __shfl_xor_sync(FULLM, o4.w, 8);
        o4.x += __shfl_xor_sync(FULLM, o4.x, 16);
        o4.y += __shfl_xor_sync(FULLM, o4.y, 16);
        o4.z += __shfl_xor_sync(FULLM, o4.z, 16);
        o4.w += __shfl_xor_sync(FULLM, o4.w, 16);
        if (hs == 0) {
            ((float4*)(g_cv + (size_t)m * CMID))[cq] = o4;
            ps.x += o4.x; ps.y += o4.y; ps.z += o4.z; ps.w += o4.w;
            pq.x = fmaf(o4.x, o4.x, pq.x); pq.y = fmaf(o4.y, o4.y, pq.y);
            pq.z = fmaf(o4.z, o4.z, pq.z); pq.w = fmaf(o4.w, o4.w, pq.w);
        }
        __syncwarp();
    }
    if (hs == 0) { redS[warp][cq] = ps; redQ[warp][cq] = pq; }
    __syncthreads();
    if (warp == 0 && lane < 8) {
        float4 s = make_float4(0.f, 0.f, 0.f, 0.f);
        float4 q = make_float4(0.f, 0.f, 0.f, 0.f);
        #pragma unroll
        for (int w = 0; w < 8; w++) {
            float4 a = redS[w][lane], b = redQ[w][lane];
            s.x += a.x; s.y += a.y; s.z += a.z; s.w += a.w;
            q.x += b.x; q.y += b.y; q.z += b.z; q.w += b.w;
        }
        atomicAdd(&g_stats[64 + lane*4 + 0], s.x);
        atomicAdd(&g_stats[64 + lane*4 + 1], s.y);
        atomicAdd(&g_stats[64 + lane*4 + 2], s.z);
        atomicAdd(&g_stats[64 + lane*4 + 3], s.w);
        atomicAdd(&g_stats[96 + lane*4 + 0], q.x);
        atomicAdd(&g_stats[96 + lane*4 + 1], q.y);
        atomicAdd(&g_stats[96 + lane*4 + 2], q.z);
        atomicAdd(&g_stats[96 + lane*4 + 3], q.w);
    }
}

// ---------- BN2+lrelu, x2 @ w_u2(32,128) -> d_out, 4 rows/warp ----------
__global__ __launch_bounds__(256, 4) void k_unary2(const float* __restrict__ w_u2,
                                                   const float* __restrict__ gc,
                                                   const float* __restrict__ bc,
                                                   float invM,
                                                   float* __restrict__ out, int M) {
    __shared__ float4 sw2[32 * 32];    // [c][lane] = w_u2[c*128 + 4*lane..], 16 KB
    __shared__ float ys[8][4][CMID];   // [warp][row][channel], 4 KB
    __shared__ float bn2[64];
    __shared__ float4 red4[2][8][32];
    int t = threadIdx.x;
    if (t < 32) {
        float s = g_stats[64 + t], q = g_stats[96 + t];
        float mm = s * invM;
        float v = q * invM - mm * mm;
        float is = rsqrtf(v + BNEPS);
        float sc = is * gc[t];
        bn2[t] = sc;
        bn2[32 + t] = bc[t] - mm * sc;
    }
    for (int i = t; i < 1024; i += 256) sw2[i] = ((const float4*)w_u2)[i];
    __syncthreads();
    int warp = t >> 5, lane = t & 31;
    int G = (M + 3) >> 2;
    int wgid = blockIdx.x * 8 + warp;
    int nw = gridDim.x * 8;
    float4 ps = make_float4(0.f, 0.f, 0.f, 0.f);
    float4 pq = make_float4(0.f, 0.f, 0.f, 0.f);
    for (int g = wgid; g < G; g += nw) {
        int m0 = g << 2;
        // stage 4 BN'd rows: 32 float4s (4 rows x 8 chunks), 1 per lane
        {
            int row = lane >> 3, ch = lane & 7;
            int m = m0 + row;
            float4 v = make_float4(0.f, 0.f, 0.f, 0.f);
            if (m < M) v = ((const float4*)g_cv)[(size_t)m * 8 + ch];
            float4 sc4 = ((const float4*)bn2)[ch];
            float4 sh4 = ((const float4*)(bn2 + 32))[ch];
            float y;
            y = fmaf(v.x, sc4.x, sh4.x); v.x = fmaxf(y, NEG * y);
            y = fmaf(v.y, sc4.y, sh4.y); v.y = fmaxf(y, NEG * y);
            y = fmaf(v.z, sc4.z, sh4.z); v.z = fmaxf(y, NEG * y);
            y = fmaf(v.w, sc4.w, sh4.w); v.w = fmaxf(y, NEG * y);
            ((float4*)ys[warp][row])[ch] = v;
        }
        __syncwarp();
        float4 acc[4];
        #pragma unroll
        for (int r = 0; r < 4; r++) acc[r] = make_float4(0.f, 0.f, 0.f, 0.f);
        #pragma unroll 4
        for (int c = 0; c < 32; c++) {
            float4 w4 = sw2[c * 32 + lane];     // conflict-free LDS.128
            #pragma unroll
            for (int r = 0; r < 4; r++) {
                float s = ys[warp][r][c];       // broadcast LDS.32
                acc[r].x = fmaf(s, w4.x, acc[r].x);
                acc[r].y = fmaf(s, w4.y, acc[r].y);
                acc[r].z = fmaf(s, w4.z, acc[r].z);
                acc[r].w = fmaf(s, w4.w, acc[r].w);
            }
        }
        #pragma unroll
        for (int r = 0; r < 4; r++) {
            int m = m0 + r;
            if (m < M) {
                ((float4*)out)[(size_t)m * 32 + lane] = acc[r];
                ps.x += acc[r].x; ps.y += acc[r].y; ps.z += acc[r].z; ps.w += acc[r].w;
                pq.x = fmaf(acc[r].x, acc[r].x, pq.x);
                pq.y = fmaf(acc[r].y, acc[r].y, pq.y);
                pq.z = fmaf(acc[r].z, acc[r].z, pq.z);
                pq.w = fmaf(acc[r].w, acc[r].w, pq.w);
            }
        }
        __syncwarp();
    }
    red4[0][warp][lane] = ps;
    red4[1][warp][lane] = pq;
    __syncthreads();
    if (warp < 2) {
        float4 s = make_float4(0.f, 0.f, 0.f, 0.f);
        #pragma unroll
        for (int w = 0; w < 8; w++) {
            float4 v = red4[warp][w][lane];
            s.x += v.x; s.y += v.y; s.z += v.z; s.w += v.w;
        }
        int base = 128 + warp * 128 + 4 * lane;   // warp0 -> sums, warp1 -> squares
        atomicAdd(&g_stats[base + 0], s.x);
        atomicAdd(&g_stats[base + 1], s.y);
        atomicAdd(&g_stats[base + 2], s.z);
        atomicAdd(&g_stats[base + 3], s.w);
    }
}

// ---------- final: bn3(x3) + s_feats, lrelu (float4, persistent grid) ----------
__global__ __launch_bounds__(256) void k_final(const float* __restrict__ sfeat,
                                               const float* __restrict__ g2,
                                               const float* __restrict__ b2,
                                               float invM,
                                               float* __restrict__ out, int M) {
    __shared__ float bn3[256];   // sc[128], sh[128]
    int t = threadIdx.x;
    if (t < 128) {
        float s = g_stats[128 + t], q = g_stats[256 + t];
        float mm = s * invM;
        float v = q * invM - mm * mm;
        float is = rsqrtf(v + BNEPS);
        float sc = is * g2[t];
        bn3[t] = sc;
        bn3[128 + t] = b2[t] - mm * sc;
    }
    __syncthreads();
    int c4 = (t & 31) * 4;
    float s0 = bn3[c4 + 0], s1 = bn3[c4 + 1], s2 = bn3[c4 + 2], s3 = bn3[c4 + 3];
    float h0 = bn3[128 + c4 + 0], h1 = bn3[128 + c4 + 1], h2 = bn3[128 + c4 + 2], h3 = bn3[128 + c4 + 3];
    int n = M * 32;                 // float4 count
    int stride = gridDim.x * 256;
    for (int i = blockIdx.x * 256 + t; i < n; i += stride) {
        float4 x = ((const float4*)out)[i];
        float4 s = ((const float4*)sfeat)[i];
        float4 r;
        float y;
        y = fmaf(x.x, s0, h0) + s.x; r.x = fmaxf(y, NEG * y);
        y = fmaf(x.y, s1, h1) + s.y; r.y = fmaxf(y, NEG * y);
        y = fmaf(x.z, s2, h2) + s.z; r.z = fmaxf(y, NEG * y);
        y = fmaf(x.w, s3, h3) + s.w; r.w = fmaxf(y, NEG * y);
        ((float4*)out)[i] = r;
    }
}

extern "C" void kernel_launch(void* const* d_in, const int* in_sizes, int n_in,
                              void* d_out, int out_size) {
    const float* q_pts  = (const float*)d_in[0];
    const float* s_pts  = (const float*)d_in[1];
    const float* sfeat  = (const float*)d_in[2];
    const int*   nidx   = (const int*)  d_in[3];
    const float* kp     = (const float*)d_in[4];
    const float* w_u1   = (const float*)d_in[5];
    const float* g_u1   = (const float*)d_in[6];
    const float* b_u1   = (const float*)d_in[7];
    const float* w_g1   = (const float*)d_in[8];
    const float* b_g1   = (const float*)d_in[9];
    const float* w_g2   = (const float*)d_in[10];
    const float* b_g2   = (const float*)d_in[11];
    const float* g_c    = (const float*)d_in[12];
    const float* b_c    = (const float*)d_in[13];
    const float* w_u2   = (const float*)d_in[14];
    const float* g_u2   = (const float*)d_in[15];
    const float* b_u2   = (const float*)d_in[16];
    float* out = (float*)d_out;

    int M = in_sizes[2] / CIN;
    float invM = 1.0f / (float)M;

    // occupancy-exact persistent grids (deterministic host queries; no alloc/sync)
    int sms = 148;
    cudaDeviceGetAttribute(&sms, cudaDevAttrMultiProcessorCount, 0);
    int b_u1n = 4, b_cv = 4, b_u2n = 4, b_fn = 4, b_b1 = 4;
    cudaOccupancyMaxActiveBlocksPerMultiprocessor(&b_u1n, k_unary1, 256, 0);
    cudaOccupancyMaxActiveBlocksPerMultiprocessor(&b_cv,  k_conv,   256, 0);
    cudaOccupancyMaxActiveBlocksPerMultiprocessor(&b_u2n, k_unary2, 256, 0);
    cudaOccupancyMaxActiveBlocksPerMultiprocessor(&b_fn,  k_final,  256, 0);
    cudaOccupancyMaxActiveBlocksPerMultiprocessor(&b_b1,  k_bn1,    256, 0);
    int g_u1n = sms * (b_u1n > 0 ? b_u1n : 1);
    int g_cvn = sms * (b_cv  > 0 ? b_cv  : 1);
    int g_u2n = sms * (b_u2n > 0 ? b_u2n : 1);
    int g_fnn = sms * (b_fn  > 0 ? b_fn  : 1);
    int g_b1n = sms * (b_b1  > 0 ? b_b1  : 1);

    k_prep<<<2 * sms, 256>>>(s_pts, M);
    k_unary1<<<g_u1n, 256>>>(sfeat, w_u1, M);
    k_bn1<<<g_b1n, 256>>>(g_u1, b_u1, invM, M);
    k_conv<<<g_cvn, 256>>>(q_pts, nidx, kp, w_g1, b_g1, w_g2, b_g2, M);
    k_unary2<<<g_u2n, 256>>>(w_u2, g_c, b_c, invM, out, M);
    k_final<<<g_fnn, 256>>>(sfeat, g_u2, b_u2, invM, out, M);
}

// round 17
// speedup vs baseline: 1.0457x; 1.0457x over previous
#include <cuda_runtime.h>
#include <cuda_bf16.h>

#define MMAX 50000
#define HNB 32
#define CIN 128
#define CMID 32
#define KPTS 15
#define CPG 16
#define BNEPS 1e-5f
#define NEG 0.1f
#define FULLM 0xffffffffu

// scratch (device globals; no allocation allowed)
__device__ float g_x1[MMAX * CMID];   // unary1 output (raw, then BN1+lrelu in place)
__device__ float g_cv[MMAX * CMID];   // conv output (raw pre-BN)
__device__ float4 g_pts4[MMAX];       // padded support points (x,y,z,0)
// stats raw sums: [0:32) sum1 [32:64) sq1 [64:96) sum2 [96:128) sq2 [128:256) sum3 [256:384) sq3
__device__ float g_stats[384];

// ---------- prep: zero stats + pad s_pts to float4 ----------
__global__ __launch_bounds__(256) void k_prep(const float* __restrict__ s_pts, int M) {
    if (blockIdx.x == 0) {
        for (int i = threadIdx.x; i < 384; i += 256) g_stats[i] = 0.f;
    }
    int stride = gridDim.x * blockDim.x;
    for (int i = blockIdx.x * blockDim.x + threadIdx.x; i < M; i += stride) {
        g_pts4[i] = make_float4(s_pts[3*i], s_pts[3*i + 1], s_pts[3*i + 2], 0.f);
    }
}

// ---------- unary1: y1 = s_feats(M,128) @ w_u1(128,32), 4 rows/warp ----------
__global__ __launch_bounds__(256, 4) void k_unary1(const float* __restrict__ sfeat,
                                                   const float* __restrict__ w_u1, int M) {
    __shared__ float4 swt[32 * 32];     // [chunk q][c] = w[4q..4q+3][c], 16 KB
    __shared__ float4 xs[8][4][32];     // [warp][row][chunk], 16 KB
    __shared__ float red[8][2][CMID];
    int t = threadIdx.x;
    for (int i = t; i < CIN * CMID; i += 256) {
        int c = i & 31, ii = i >> 5;
        ((float*)&swt[(ii >> 2) * 32 + c])[ii & 3] = w_u1[i];
    }
    __syncthreads();
    int warp = t >> 5, lane = t & 31;
    int G = (M + 3) >> 2;
    int wgid = blockIdx.x * 8 + warp;
    int nw = gridDim.x * 8;
    float lsum = 0.f, lsq = 0.f;
    for (int g = wgid; g < G; g += nw) {
        int m0 = g << 2;
        #pragma unroll
        for (int r = 0; r < 4; r++) {
            int m = m0 + r;
            float4 v = make_float4(0.f, 0.f, 0.f, 0.f);
            if (m < M) v = ((const float4*)(sfeat + (size_t)m * CIN))[lane];
            xs[warp][r][lane] = v;
        }
        __syncwarp();
        float acc[4] = {0.f, 0.f, 0.f, 0.f};
        #pragma unroll 4
        for (int q = 0; q < 32; q++) {
            float4 w4 = swt[q * 32 + lane];      // conflict-free LDS.128
            #pragma unroll
            for (int r = 0; r < 4; r++) {
                float4 x4 = xs[warp][r][q];      // broadcast LDS.128
                acc[r] = fmaf(x4.x, w4.x, acc[r]);
                acc[r] = fmaf(x4.y, w4.y, acc[r]);
                acc[r] = fmaf(x4.z, w4.z, acc[r]);
                acc[r] = fmaf(x4.w, w4.w, acc[r]);
            }
        }
        #pragma unroll
        for (int r = 0; r < 4; r++) {
            int m = m0 + r;
            if (m < M) {
                g_x1[(size_t)m * CMID + lane] = acc[r];
                lsum += acc[r];
                lsq = fmaf(acc[r], acc[r], lsq);
            }
        }
        __syncwarp();
    }
    red[warp][0][lane] = lsum; red[warp][1][lane] = lsq;
    __syncthreads();
    if (warp == 0) {
        float s = 0.f, q = 0.f;
        #pragma unroll
        for (int w = 0; w < 8; w++) { s += red[w][0][lane]; q += red[w][1][lane]; }
        atomicAdd(&g_stats[lane], s);
        atomicAdd(&g_stats[32 + lane], q);
    }
}

// ---------- bn1: apply BN1 + lrelu to g_x1 in place (float4, persistent) ----------
__global__ __launch_bounds__(256) void k_bn1(const float* __restrict__ g1,
                                             const float* __restrict__ b1,
                                             float invM, int M) {
    __shared__ float bn1[64];
    int t = threadIdx.x;
    if (t < 32) {
        float s = g_stats[t], q = g_stats[32 + t];
        float mm = s * invM;
        float v = q * invM - mm * mm;
        float is = rsqrtf(v + BNEPS);
        float sc = is * g1[t];
        bn1[t] = sc;
        bn1[32 + t] = b1[t] - mm * sc;
    }
    __syncthreads();
    int n = M * 8;                     // float4 count
    int stride = gridDim.x * 256;
    for (int i = blockIdx.x * 256 + t; i < n; i += stride) {
        int ch = i & 7;
        float4 sc4 = ((const float4*)bn1)[ch];
        float4 sh4 = ((const float4*)(bn1 + 32))[ch];
        float4 v = ((const float4*)g_x1)[i];
        float y;
        y = fmaf(v.x, sc4.x, sh4.x); v.x = fmaxf(y, NEG * y);
        y = fmaf(v.y, sc4.y, sh4.y); v.y = fmaxf(y, NEG * y);
        y = fmaf(v.z, sc4.z, sh4.z); v.z = fmaxf(y, NEG * y);
        y = fmaf(v.w, sc4.w, sh4.w); v.w = fmaxf(y, NEG * y);
        ((float4*)g_x1)[i] = v;
    }
}

// ---------- KPInv conv: one warp per point, register-resident gather ----------
__global__ __launch_bounds__(256) void k_conv(const float* __restrict__ q_pts,
                                              const int* __restrict__ nidx,
                                              const float* __restrict__ kp,
                                              const float* __restrict__ w_g1,
                                              const float* __restrict__ b_g1,
                                              const float* __restrict__ w_g2,
                                              const float* __restrict__ b_g2,
                                              int M) {
    __shared__ float4 wg1q[64];         // [u][cq]: w_g1 transposed, float4 over c
    __shared__ float kps[KPTS * 3];
    __shared__ float kpn[KPTS];
    __shared__ float bg1s[8];
    __shared__ float wg2s[8 * 30];
    __shared__ float bg2s[30];
    __shared__ float wbuf[8][32];
    __shared__ float2 abuf[8][32];
    __shared__ float4 redS[8][8], redQ[8][8];
    int t = threadIdx.x;
    if (t < KPTS * 3) kps[t] = kp[t];
    if (t >= 64 && t < 64 + KPTS) {
        int k = t - 64;
        kpn[k] = kp[k*3]*kp[k*3] + kp[k*3+1]*kp[k*3+1] + kp[k*3+2]*kp[k*3+2];
    }
    for (int i = t; i < 256; i += blockDim.x) {
        int u = i >> 5, c = i & 31;
        ((float*)wg1q)[u * 32 + c] = w_g1[c * 8 + u];
    }
    if (t >= 96 && t < 104) bg1s[t - 96] = b_g1[t - 96];
    for (int i = t; i < 240; i += blockDim.x) wg2s[i] = w_g2[i];
    if (t >= 128 && t < 158) bg2s[t - 128] = b_g2[t - 128];
    __syncthreads();

    int warp = t >> 5, lane = t & 31;
    int hs = lane >> 3, cq = lane & 7, hi = cq >> 2;
    int wgid = blockIdx.x * 8 + warp;
    int nw = gridDim.x * 8;
    float4 ps = make_float4(0.f, 0.f, 0.f, 0.f);
    float4 pq = make_float4(0.f, 0.f, 0.f, 0.f);

    for (int m = wgid; m < M; m += nw) {
        // lane = neighbor h: index + geometry (position via one LDG.128)
        int j = nidx[(size_t)m * HNB + lane];
        int off = j << 5;
        float qx = q_pts[m*3], qy = q_pts[m*3+1], qz = q_pts[m*3+2];
        float4 sp = g_pts4[j];
        float nx = sp.x - qx;
        float ny = sp.y - qy;
        float nz = sp.z - qz;
        float n2 = nx*nx + ny*ny + nz*nz;
        // gather float4 (already BN'd+lrelu'd) into REGISTERS: lane = (h = 4i+hs, chans cq*4..+3)
        float4 v[8];
        float4 cm = make_float4(-3.4e38f, -3.4e38f, -3.4e38f, -3.4e38f);
        #pragma unroll
        for (int i = 0; i < 8; i++) {
            int h = i * 4 + hs;
            int oh = __shfl_sync(FULLM, off, h);
            v[i] = *(const float4*)(g_x1 + oh + cq * 4);
            cm.x = fmaxf(cm.x, v[i].x); cm.y = fmaxf(cm.y, v[i].y);
            cm.z = fmaxf(cm.z, v[i].z); cm.w = fmaxf(cm.w, v[i].w);
        }
        // reduce max over hs groups (xor 8, 16)
        cm.x = fmaxf(cm.x, __shfl_xor_sync(FULLM, cm.x, 8));
        cm.y = fmaxf(cm.y, __shfl_xor_sync(FULLM, cm.y, 8));
        cm.z = fmaxf(cm.z, __shfl_xor_sync(FULLM, cm.z, 8));
        cm.w = fmaxf(cm.w, __shfl_xor_sync(FULLM, cm.w, 8));
        cm.x = fmaxf(cm.x, __shfl_xor_sync(FULLM, cm.x, 16));
        cm.y = fmaxf(cm.y, __shfl_xor_sync(FULLM, cm.y, 16));
        cm.z = fmaxf(cm.z, __shfl_xor_sync(FULLM, cm.z, 16));
        cm.w = fmaxf(cm.w, __shfl_xor_sync(FULLM, cm.w, 16));
        // MLP: per-lane partial dot over 4 channels, sum over cq via xor 1,2,4
        float hp[8];
        #pragma unroll
        for (int u = 0; u < 8; u++) {
            float4 w4 = wg1q[u * 8 + cq];
            float p = cm.x * w4.x;
            p = fmaf(cm.y, w4.y, p);
            p = fmaf(cm.z, w4.z, p);
            p = fmaf(cm.w, w4.w, p);
            hp[u] = p;
        }
        #pragma unroll
        for (int o = 1; o <= 4; o <<= 1)
            #pragma unroll
            for (int u = 0; u < 8; u++) hp[u] += __shfl_xor_sync(FULLM, hp[u], o);
        // w[t] = b_g2[t] + lrelu(hp+b) @ w_g2, layout (K,G): w[k][g] at 2k+g
        float wt = 0.f;
        if (lane < 30) {
            wt = bg2s[lane];
            #pragma unroll
            for (int u = 0; u < 8; u++) {
                float vv = hp[u] + bg1s[u];
                vv = fmaxf(vv, NEG * vv);
                wt = fmaf(vv, wg2s[u * 30 + lane], wt);
            }
        }
        wbuf[warp][lane] = wt;
        __syncwarp();
        // collapse K with transient influence (lane = h)
        float a0 = 0.f, a1 = 0.f;
        #pragma unroll
        for (int k = 0; k < KPTS; k++) {
            float dot = nx*kps[k*3] + ny*kps[k*3+1] + nz*kps[k*3+2];
            float d2 = n2 + kpn[k] - 2.f * dot;
            float d = sqrtf(fmaxf(d2, 0.f));
            float infl = fmaxf(1.f - d, 0.f);
            a0 = fmaf(wbuf[warp][2*k],     infl, a0);
            a1 = fmaf(wbuf[warp][2*k + 1], infl, a1);
        }
        abuf[warp][lane] = make_float2(a0, a1);
        __syncwarp();
        // out[c] = sum_h a[h][g(c)] * nf[h][c], registers: lane = (hs, cq)
        float4 o4 = make_float4(0.f, 0.f, 0.f, 0.f);
        #pragma unroll
        for (int i = 0; i < 8; i++) {
            int h = i * 4 + hs;
            float a = ((const float*)abuf[warp])[h * 2 + hi];  // group select in addr
            o4.x = fmaf(a, v[i].x, o4.x);
            o4.y = fmaf(a, v[i].y, o4.y);
            o4.z = fmaf(a, v[i].z, o4.z);
            o4.w = fmaf(a, v[i].w, o4.w);
        }
        o4.x += __shfl_xor_sync(FULLM, o4.x, 8);
        o4.y += __shfl_xor_sync(FULLM, o4.y, 8);
        o4.z += __shfl_xor_sync(FULLM, o4.z, 8);
        o4.w += __shfl_xor_sync(FULLM, o4.w, 8);
        o4.x += __shfl_xor_sync(FULLM, o4.x, 16);
        o4.y += __shfl_xor_sync(FULLM, o4.y, 16);
        o4.z += __shfl_xor_sync(FULLM, o4.z, 16);
        o4.w += __shfl_xor_sync(FULLM, o4.w, 16);
        if (hs == 0) {
            ((float4*)(g_cv + (size_t)m * CMID))[cq] = o4;
            ps.x += o4.x; ps.y += o4.y; ps.z += o4.z; ps.w += o4.w;
            pq.x = fmaf(o4.x, o4.x, pq.x); pq.y = fmaf(o4.y, o4.y, pq.y);
            pq.z = fmaf(o4.z, o4.z, pq.z); pq.w = fmaf(o4.w, o4.w, pq.w);
        }
        __syncwarp();
    }
    if (hs == 0) { redS[warp][cq] = ps; redQ[warp][cq] = pq; }
    __syncthreads();
    if (warp == 0 && lane < 8) {
        float4 s = make_float4(0.f, 0.f, 0.f, 0.f);
        float4 q = make_float4(0.f, 0.f, 0.f, 0.f);
        #pragma unroll
        for (int w = 0; w < 8; w++) {
            float4 a = redS[w][lane], b = redQ[w][lane];
            s.x += a.x; s.y += a.y; s.z += a.z; s.w += a.w;
            q.x += b.x; q.y += b.y; q.z += b.z; q.w += b.w;
        }
        atomicAdd(&g_stats[64 + lane*4 + 0], s.x);
        atomicAdd(&g_stats[64 + lane*4 + 1], s.y);
        atomicAdd(&g_stats[64 + lane*4 + 2], s.z);
        atomicAdd(&g_stats[64 + lane*4 + 3], s.w);
        atomicAdd(&g_stats[96 + lane*4 + 0], q.x);
        atomicAdd(&g_stats[96 + lane*4 + 1], q.y);
        atomicAdd(&g_stats[96 + lane*4 + 2], q.z);
        atomicAdd(&g_stats[96 + lane*4 + 3], q.w);
    }
}

// ---------- BN2+lrelu, x2 @ w_u2(32,128) -> d_out, 4 rows/warp ----------
__global__ __launch_bounds__(256, 4) void k_unary2(const float* __restrict__ w_u2,
                                                   const float* __restrict__ gc,
                                                   const float* __restrict__ bc,
                                                   float invM,
                                                   float* __restrict__ out, int M) {
    __shared__ float4 sw2[32 * 32];    // [c][lane] = w_u2[c*128 + 4*lane..], 16 KB
    __shared__ float ys[8][4][CMID];   // [warp][row][channel], 4 KB
    __shared__ float bn2[64];
    __shared__ float4 red4[2][8][32];
    int t = threadIdx.x;
    if (t < 32) {
        float s = g_stats[64 + t], q = g_stats[96 + t];
        float mm = s * invM;
        float v = q * invM - mm * mm;
        float is = rsqrtf(v + BNEPS);
        float sc = is * gc[t];
        bn2[t] = sc;
        bn2[32 + t] = bc[t] - mm * sc;
    }
    for (int i = t; i < 1024; i += 256) sw2[i] = ((const float4*)w_u2)[i];
    __syncthreads();
    int warp = t >> 5, lane = t & 31;
    int G = (M + 3) >> 2;
    int wgid = blockIdx.x * 8 + warp;
    int nw = gridDim.x * 8;
    float4 ps = make_float4(0.f, 0.f, 0.f, 0.f);
    float4 pq = make_float4(0.f, 0.f, 0.f, 0.f);
    for (int g = wgid; g < G; g += nw) {
        int m0 = g << 2;
        // stage 4 BN'd rows: 32 float4s (4 rows x 8 chunks), 1 per lane
        {
            int row = lane >> 3, ch = lane & 7;
            int m = m0 + row;
            float4 v = make_float4(0.f, 0.f, 0.f, 0.f);
            if (m < M) v = ((const float4*)g_cv)[(size_t)m * 8 + ch];
            float4 sc4 = ((const float4*)bn2)[ch];
            float4 sh4 = ((const float4*)(bn2 + 32))[ch];
            float y;
            y = fmaf(v.x, sc4.x, sh4.x); v.x = fmaxf(y, NEG * y);
            y = fmaf(v.y, sc4.y, sh4.y); v.y = fmaxf(y, NEG * y);
            y = fmaf(v.z, sc4.z, sh4.z); v.z = fmaxf(y, NEG * y);
            y = fmaf(v.w, sc4.w, sh4.w); v.w = fmaxf(y, NEG * y);
            ((float4*)ys[warp][row])[ch] = v;
        }
        __syncwarp();
        float4 acc[4];
        #pragma unroll
        for (int r = 0; r < 4; r++) acc[r] = make_float4(0.f, 0.f, 0.f, 0.f);
        #pragma unroll 4
        for (int c = 0; c < 32; c++) {
            float4 w4 = sw2[c * 32 + lane];     // conflict-free LDS.128
            #pragma unroll
            for (int r = 0; r < 4; r++) {
                float s = ys[warp][r][c];       // broadcast LDS.32
                acc[r].x = fmaf(s, w4.x, acc[r].x);
                acc[r].y = fmaf(s, w4.y, acc[r].y);
                acc[r].z = fmaf(s, w4.z, acc[r].z);
                acc[r].w = fmaf(s, w4.w, acc[r].w);
            }
        }
        #pragma unroll
        for (int r = 0; r < 4; r++) {
            int m = m0 + r;
            if (m < M) {
                ((float4*)out)[(size_t)m * 32 + lane] = acc[r];
                ps.x += acc[r].x; ps.y += acc[r].y; ps.z += acc[r].z; ps.w += acc[r].w;
                pq.x = fmaf(acc[r].x, acc[r].x, pq.x);
                pq.y = fmaf(acc[r].y, acc[r].y, pq.y);
                pq.z = fmaf(acc[r].z, acc[r].z, pq.z);
                pq.w = fmaf(acc[r].w, acc[r].w, pq.w);
            }
        }
        __syncwarp();
    }
    red4[0][warp][lane] = ps;
    red4[1][warp][lane] = pq;
    __syncthreads();
    if (warp < 2) {
        float4 s = make_float4(0.f, 0.f, 0.f, 0.f);
        #pragma unroll
        for (int w = 0; w < 8; w++) {
            float4 v = red4[warp][w][lane];
            s.x += v.x; s.y += v.y; s.z += v.z; s.w += v.w;
        }
        int base = 128 + warp * 128 + 4 * lane;   // warp0 -> sums, warp1 -> squares
        atomicAdd(&g_stats[base + 0], s.x);
        atomicAdd(&g_stats[base + 1], s.y);
        atomicAdd(&g_stats[base + 2], s.z);
        atomicAdd(&g_stats[base + 3], s.w);
    }
}

// ---------- final: bn3(x3) + s_feats, lrelu (float4, persistent grid) ----------
__global__ __launch_bounds__(256) void k_final(const float* __restrict__ sfeat,
                                               const float* __restrict__ g2,
                                               const float* __restrict__ b2,
                                               float invM,
                                               float* __restrict__ out, int M) {
    __shared__ float bn3[256];   // sc[128], sh[128]
    int t = threadIdx.x;
    if (t < 128) {
        float s = g_stats[128 + t], q = g_stats[256 + t];
        float mm = s * invM;
        float v = q * invM - mm * mm;
        float is = rsqrtf(v + BNEPS);
        float sc = is * g2[t];
        bn3[t] = sc;
        bn3[128 + t] = b2[t] - mm * sc;
    }
    __syncthreads();
    int c4 = (t & 31) * 4;
    float s0 = bn3[c4 + 0], s1 = bn3[c4 + 1], s2 = bn3[c4 + 2], s3 = bn3[c4 + 3];
    float h0 = bn3[128 + c4 + 0], h1 = bn3[128 + c4 + 1], h2 = bn3[128 + c4 + 2], h3 = bn3[128 + c4 + 3];
    int n = M * 32;                 // float4 count
    int stride = gridDim.x * 256;
    for (int i = blockIdx.x * 256 + t; i < n; i += stride) {
        float4 x = ((const float4*)out)[i];
        float4 s = ((const float4*)sfeat)[i];
        float4 r;
        float y;
        y = fmaf(x.x, s0, h0) + s.x; r.x = fmaxf(y, NEG * y);
        y = fmaf(x.y, s1, h1) + s.y; r.y = fmaxf(y, NEG * y);
        y = fmaf(x.z, s2, h2) + s.z; r.z = fmaxf(y, NEG * y);
        y = fmaf(x.w, s3, h3) + s.w; r.w = fmaxf(y, NEG * y);
        ((float4*)out)[i] = r;
    }
}

extern "C" void kernel_launch(void* const* d_in, const int* in_sizes, int n_in,
                              void* d_out, int out_size) {
    const float* q_pts  = (const float*)d_in[0];
    const float* s_pts  = (const float*)d_in[1];
    const float* sfeat  = (const float*)d_in[2];
    const int*   nidx   = (const int*)  d_in[3];
    const float* kp     = (const float*)d_in[4];
    const float* w_u1   = (const float*)d_in[5];
    const float* g_u1   = (const float*)d_in[6];
    const float* b_u1   = (const float*)d_in[7];
    const float* w_g1   = (const float*)d_in[8];
    const float* b_g1   = (const float*)d_in[9];
    const float* w_g2   = (const float*)d_in[10];
    const float* b_g2   = (const float*)d_in[11];
    const float* g_c    = (const float*)d_in[12];
    const float* b_c    = (const float*)d_in[13];
    const float* w_u2   = (const float*)d_in[14];
    const float* g_u2   = (const float*)d_in[15];
    const float* b_u2   = (const float*)d_in[16];
    float* out = (float*)d_out;

    int M = in_sizes[2] / CIN;
    float invM = 1.0f / (float)M;

    // occupancy-exact persistent grids (deterministic host queries; no alloc/sync)
    int sms = 148;
    cudaDeviceGetAttribute(&sms, cudaDevAttrMultiProcessorCount, 0);
    int b_u1n = 4, b_cv = 4, b_u2n = 4, b_fn = 4, b_b1 = 4;
    cudaOccupancyMaxActiveBlocksPerMultiprocessor(&b_u1n, k_unary1, 256, 0);
    cudaOccupancyMaxActiveBlocksPerMultiprocessor(&b_cv,  k_conv,   256, 0);
    cudaOccupancyMaxActiveBlocksPerMultiprocessor(&b_u2n, k_unary2, 256, 0);
    cudaOccupancyMaxActiveBlocksPerMultiprocessor(&b_fn,  k_final,  256, 0);
    cudaOccupancyMaxActiveBlocksPerMultiprocessor(&b_b1,  k_bn1,    256, 0);
    int g_u1n = sms * (b_u1n > 0 ? b_u1n : 1);
    int g_cvn = sms * (b_cv  > 0 ? b_cv  : 1);
    int g_u2n = sms * (b_u2n > 0 ? b_u2n : 1);
    int g_fnn = sms * (b_fn  > 0 ? b_fn  : 1);
    int g_b1n = sms * (b_b1  > 0 ? b_b1  : 1);

    k_prep<<<2 * sms, 256>>>(s_pts, M);
    k_unary1<<<g_u1n, 256>>>(sfeat, w_u1, M);
    k_bn1<<<g_b1n, 256>>>(g_u1, b_u1, invM, M);
    k_conv<<<g_cvn, 256>>>(q_pts, nidx, kp, w_g1, b_g1, w_g2, b_g2, M);
    k_unary2<<<g_u2n, 256>>>(w_u2, g_c, b_c, invM, out, M);
    k_final<<<g_fnn, 256>>>(sfeat, g_u2, b_u2, invM, out, M);
}